// round 7
// baseline (speedup 1.0000x reference)
#include <cuda_runtime.h>
#include <cuda_fp16.h>

#define BATCH   2048
#define TSTEPS  128
#define SLEN    256
#define HID     64
#define EMB     32
#define VOCAB   29
#define GATES   256          // 4*HID
#define ROWH2   36           // enc row stride in half2 units (144 B, conflict-free)

// Precomputed tables (device globals — allocation-free scratch)
__device__ float   g_vocabW[VOCAB * GATES];   // emb@W_ih[:, :32]^T + b_ih + b_hh  (fp32)
__device__ __half2 g_WTh[64 * GATES];         // g_WTh[k2*256+j] = (WT[2k2][j], WT[2k2+1][j]) fp16
__device__ float   g_fcT[128 * 32];           // fcT[d][v] = fc_W[v][d] (v<29 else 0); d: [h(64), ctx(64)]

struct __align__(16) Smem {
    __half2 ench[SLEN * ROWH2];  // 36864 B  enc in fp16 pairs, padded rows
    float   cp[8][HID];          //  2048 B  context partials per warp
    float   h[2][HID];           //   512 B  double-buffered hidden state
    float   ctx[HID];            //   256 B
    float   fp[8][32];           //  1024 B  fc partials
    float   wsum[8];             //    32 B
    int     ybuf[TSTEPS];        //   512 B
};  // ~41.2 KB -> 2 CTAs/SM

__global__ void setup_vocabW(const float* __restrict__ emb,
                             const float* __restrict__ W_ih,
                             const float* __restrict__ b_ih,
                             const float* __restrict__ b_hh) {
    int v = blockIdx.x, j = threadIdx.x;
    float acc = b_ih[j] + b_hh[j];
#pragma unroll
    for (int e = 0; e < EMB; e++)
        acc += emb[v * EMB + e] * W_ih[j * (EMB + HID) + e];
    g_vocabW[v * GATES + j] = acc;
}

__device__ __forceinline__ float wt_elem(const float* W_ih, const float* W_hh, int k, int j) {
    // x = [ctx(64), h(64)]
    return (k < HID) ? W_ih[j * (EMB + HID) + EMB + k] : W_hh[j * HID + (k - HID)];
}

__global__ void setup_WTh(const float* __restrict__ W_ih,
                          const float* __restrict__ W_hh) {
    int k2 = blockIdx.x, j = threadIdx.x;   // k2 in [0,64)
    float w0 = wt_elem(W_ih, W_hh, 2 * k2 + 0, j);
    float w1 = wt_elem(W_ih, W_hh, 2 * k2 + 1, j);
    g_WTh[k2 * GATES + j] = __floats2half2_rn(w0, w1);
}

__global__ void setup_fcT(const float* __restrict__ fc_W) {
    int d = blockIdx.x, v = threadIdx.x;   // grid 128, block 32
    g_fcT[d * 32 + v] = (v < VOCAB) ? fc_W[v * 2 * HID + d] : 0.0f;
}

__device__ __forceinline__ float fsigmoid(float x) {
    return __fdividef(1.0f, 1.0f + __expf(-fmaxf(x, -80.0f)));
}
__device__ __forceinline__ float ftanh(float x) {
    float e = __expf(fminf(2.0f * x, 80.0f));
    return 1.0f - __fdividef(2.0f, e + 1.0f);
}

__global__ __launch_bounds__(256, 2)
void decoder_kernel(const int* __restrict__ y,
                    const float* __restrict__ h0,
                    const float* __restrict__ c0,
                    const float* __restrict__ enc,
                    const float* __restrict__ fc_b,
                    float* __restrict__ out) {
    extern __shared__ char smem_raw[];
    Smem& S = *reinterpret_cast<Smem*>(smem_raw);

    const int tid  = threadIdx.x;
    const int lane = tid & 31;
    const int wid  = tid >> 5;
    const int b    = blockIdx.x;

    // Gate ownership: thread handles gate quadrant q of hidden dim j.
    // The 4 gates of dim j live in 4 ADJACENT lanes of one warp.
    const int q    = tid & 3;          // 0:i 1:f 2:g 3:o
    const int j    = tid >> 2;         // hidden dim [0,64)
    const int gidx = q * 64 + j;       // row in the canonical 256-gate order

    // ---- Gate weights in registers: thread holds full 128-weight column as 64 half2 ----
    __half2 W2[64];
#pragma unroll
    for (int i = 0; i < 64; i++)
        W2[i] = g_WTh[i * GATES + gidx];

    // ---- Prologue: enc -> fp16 shared (padded rows) ----
    {
        const float4* esrc = reinterpret_cast<const float4*>(enc) + (size_t)b * (SLEN * HID / 4);
#pragma unroll
        for (int it = 0; it < 16; it++) {
            int idx = tid + it * 256;              // 4096 float4s
            int s = idx >> 4, qq = idx & 15;       // qq indexes 4 floats within row
            float4 v = esrc[idx];
            __half2 a  = __floats2half2_rn(v.x, v.y);
            __half2 c2 = __floats2half2_rn(v.z, v.w);
            __half2* dst = &S.ench[s * ROWH2 + 2 * qq];
            dst[0] = a; dst[1] = c2;
        }
    }
    float c_reg = (q == 0) ? c0[b * HID + j] : 0.0f;
    if (tid < HID) S.h[0][tid] = h0[b * HID + tid];
    if (tid < TSTEPS) S.ybuf[tid] = y[b * TSTEPS + tid];
    __syncthreads();

    const float4* ctxF4 = reinterpret_cast<const float4*>(S.ctx);
    const float4* erow4 = reinterpret_cast<const float4*>(&S.ench[tid * ROWH2]);

    // ---- Timestep loop ----
    for (int t = 0; t < TSTEPS; t++) {
        const int oldb = t & 1, newb = oldb ^ 1;
        const float4* hOld4 = reinterpret_cast<const float4*>(S.h[oldb]);

        // Phase A: score[s=tid] = enc16[s,:].h ; p = exp(score); warp sums.
        float p;
        {
            float a0 = 0.f, a1 = 0.f;
#pragma unroll
            for (int k = 0; k < 8; k++) {
                float4 ev = erow4[k];
                const __half2* eh = reinterpret_cast<const __half2*>(&ev);
                float4 h0v = hOld4[2 * k], h1v = hOld4[2 * k + 1];
                float2 e0 = __half22float2(eh[0]);
                float2 e1 = __half22float2(eh[1]);
                float2 e2 = __half22float2(eh[2]);
                float2 e3 = __half22float2(eh[3]);
                a0 += e0.x * h0v.x + e0.y * h0v.y + e1.x * h0v.z + e1.y * h0v.w;
                a1 += e2.x * h1v.x + e2.y * h1v.y + e3.x * h1v.z + e3.y * h1v.w;
            }
            p = __expf(a0 + a1);
            float ws = p;
#pragma unroll
            for (int o = 16; o; o >>= 1) ws += __shfl_xor_sync(~0u, ws, o);
            if (lane == 0) S.wsum[wid] = ws;
        }

        // Phase B (no barrier: uses only own-warp p via shuffle + read-only ench).
        // Warp w covers s in [32w,32w+32); lane owns h pair (2*lane, 2*lane+1).
        {
            float cx = 0.f, cy = 0.f;
            const __half2* bbase = &S.ench[(wid * 32) * ROWH2 + lane];
#pragma unroll
            for (int i = 0; i < 32; i++) {
                float ps = __shfl_sync(~0u, p, i);
                float2 e = __half22float2(bbase[i * ROWH2]);
                cx += ps * e.x;
                cy += ps * e.y;
            }
            *reinterpret_cast<float2*>(&S.cp[wid][2 * lane]) = make_float2(cx, cy);
        }
        __syncthreads();   // (1)

        // Phase C: reduce partials + normalize -> ctx
        if (tid < HID) {
            float z = S.wsum[0];
#pragma unroll
            for (int i = 1; i < 8; i++) z += S.wsum[i];
            float a = 0.f;
#pragma unroll
            for (int w = 0; w < 8; w++) a += S.cp[w][tid];
            S.ctx[tid] = a * __fdividef(1.0f, z);
        }
        __syncthreads();   // (2)

        // Phase D+E fused: gate gidx 128-dot (fp16 reg weights), in-warp shuffle
        // to gather i/f/g/o of dim j, LSTM update by q==0 lanes into h[newb].
        {
            float acc0 = 0.f, acc1 = 0.f;
#pragma unroll
            for (int i = 0; i < 16; i++) {
                float4 x = ctxF4[i];
                float2 wa = __half22float2(W2[2 * i]);
                float2 wb = __half22float2(W2[2 * i + 1]);
                acc0 += wa.x * x.x + wa.y * x.y;
                acc1 += wb.x * x.z + wb.y * x.w;
            }
#pragma unroll
            for (int i = 0; i < 16; i++) {
                float4 x = hOld4[i];
                float2 wa = __half22float2(W2[32 + 2 * i]);
                float2 wb = __half22float2(W2[33 + 2 * i]);
                acc0 += wa.x * x.x + wa.y * x.y;
                acc1 += wb.x * x.z + wb.y * x.w;
            }
            int v = S.ybuf[t];
            float gate = acc0 + acc1 + __ldg(&g_vocabW[v * GATES + gidx]);
            float a = (q == 2) ? ftanh(gate) : fsigmoid(gate);

            int lb = lane & ~3;
            float ai = __shfl_sync(~0u, a, lb + 0);
            float af = __shfl_sync(~0u, a, lb + 1);
            float ag = __shfl_sync(~0u, a, lb + 2);
            float ao = __shfl_sync(~0u, a, lb + 3);
            if (q == 0) {
                c_reg = af * c_reg + ai * ag;
                S.h[newb][j] = ao * ftanh(c_reg);
            }
        }
        __syncthreads();   // (3)

        // Phase F: logits partials. warp w covers d in [16w,16w+16); lane = vocab slot.
        {
            const float4* sF4 = (wid < 4) ? reinterpret_cast<const float4*>(S.h[newb])
                                          : ctxF4;
            int qq = (wid & 3) * 4;
            float4 s0 = sF4[qq], s1 = sF4[qq + 1], s2 = sF4[qq + 2], s3 = sF4[qq + 3];
            const float* fc = &g_fcT[(wid * 16) * 32 + lane];
            float acc;
            acc  = s0.x * __ldg(fc +  0 * 32);
            acc += s0.y * __ldg(fc +  1 * 32);
            acc += s0.z * __ldg(fc +  2 * 32);
            acc += s0.w * __ldg(fc +  3 * 32);
            acc += s1.x * __ldg(fc +  4 * 32);
            acc += s1.y * __ldg(fc +  5 * 32);
            acc += s1.z * __ldg(fc +  6 * 32);
            acc += s1.w * __ldg(fc +  7 * 32);
            acc += s2.x * __ldg(fc +  8 * 32);
            acc += s2.y * __ldg(fc +  9 * 32);
            acc += s2.z * __ldg(fc + 10 * 32);
            acc += s2.w * __ldg(fc + 11 * 32);
            acc += s3.x * __ldg(fc + 12 * 32);
            acc += s3.y * __ldg(fc + 13 * 32);
            acc += s3.z * __ldg(fc + 14 * 32);
            acc += s3.w * __ldg(fc + 15 * 32);
            S.fp[wid][lane] = acc;
        }
        __syncthreads();   // (4)

        if (tid < VOCAB) {
            float acc = __ldg(&fc_b[tid]);
#pragma unroll
            for (int w = 0; w < 8; w++) acc += S.fp[w][tid];
            out[((size_t)b * TSTEPS + t) * VOCAB + tid] = acc;
        }
        // No trailing barrier: next write to S.fp is 4 barriers away; S.wsum/S.cp
        // writers in next iteration are ordered by barrier (4) + in-warp ordering.
    }
}

extern "C" void kernel_launch(void* const* d_in, const int* in_sizes, int n_in,
                              void* d_out, int out_size) {
    const int*   y     = (const int*)  d_in[0];
    const float* h0    = (const float*)d_in[1];
    const float* c0    = (const float*)d_in[2];
    const float* enc   = (const float*)d_in[3];
    const float* emb   = (const float*)d_in[4];
    const float* W_ih  = (const float*)d_in[5];
    const float* W_hh  = (const float*)d_in[6];
    const float* b_ih  = (const float*)d_in[7];
    const float* b_hh  = (const float*)d_in[8];
    const float* fc_W  = (const float*)d_in[9];
    const float* fc_b  = (const float*)d_in[10];
    float* out = (float*)d_out;
    (void)in_sizes; (void)n_in; (void)out_size;

    setup_vocabW<<<VOCAB, GATES>>>(emb, W_ih, b_ih, b_hh);
    setup_WTh<<<64, GATES>>>(W_ih, W_hh);
    setup_fcT<<<128, 32>>>(fc_W);

    cudaFuncSetAttribute(decoder_kernel,
                         cudaFuncAttributeMaxDynamicSharedMemorySize,
                         (int)sizeof(Smem));
    decoder_kernel<<<BATCH, 256, sizeof(Smem)>>>(y, h0, c0, enc, fc_b, out);
}

// round 8
// speedup vs baseline: 1.5125x; 1.5125x over previous
#include <cuda_runtime.h>
#include <cuda_fp16.h>

#define BATCH   2048
#define TSTEPS  128
#define SLEN    256
#define HID     64
#define EMB     32
#define VOCAB   29
#define GATES   256          // 4*HID
#define ENCPAD  68           // enc row stride in floats (272 B, conflict-free: 68 mod 32 = 4)

typedef unsigned long long u64;

// f32x2 packed-FMA helpers (sm_100+ PTX; ptxas never emits FFMA2 from C++)
__device__ __forceinline__ u64 pk2(float x, float y) {
    u64 r; asm("mov.b64 %0, {%1, %2};" : "=l"(r) : "f"(x), "f"(y)); return r;
}
__device__ __forceinline__ float2 up2(u64 v) {
    float2 r; asm("mov.b64 {%0, %1}, %2;" : "=f"(r.x), "=f"(r.y) : "l"(v)); return r;
}
__device__ __forceinline__ void fma2(u64& d, u64 a, u64 b) {
    asm("fma.rn.f32x2 %0, %1, %2, %0;" : "+l"(d) : "l"(a), "l"(b));
}

// Precomputed tables (device globals — allocation-free scratch)
__device__ float   g_vocabW[VOCAB * GATES];   // emb@W_ih[:, :32]^T + b_ih + b_hh  (fp32)
__device__ __half2 g_WTh[64 * GATES];         // g_WTh[k2*256+j] = (WT[2k2][j], WT[2k2+1][j]) fp16
__device__ float   g_fcT[128 * 32];           // fcT[d][v] = fc_W[v][d] (v<29 else 0); d: [h(64), ctx(64)]

struct __align__(16) Smem {
    float   enc[SLEN * ENCPAD];  // 69632 B  fp32, padded rows
    u64     pp[SLEN];            //  2048 B  (p,p) packed pairs
    float   cp[8][2][HID];       //  4096 B  context partials [warp][s-parity][h]
    float   h[2][HID];           //   512 B  double-buffered hidden state
    float   ctx[HID];            //   256 B
    float   fp[8][32];           //  1024 B  fc partials
    float   wsum[8];             //    32 B
    int     ybuf[TSTEPS];        //   512 B
};  // ~78.1 KB -> 2 CTAs/SM

__global__ void setup_vocabW(const float* __restrict__ emb,
                             const float* __restrict__ W_ih,
                             const float* __restrict__ b_ih,
                             const float* __restrict__ b_hh) {
    int v = blockIdx.x, j = threadIdx.x;
    float acc = b_ih[j] + b_hh[j];
#pragma unroll
    for (int e = 0; e < EMB; e++)
        acc += emb[v * EMB + e] * W_ih[j * (EMB + HID) + e];
    g_vocabW[v * GATES + j] = acc;
}

__device__ __forceinline__ float wt_elem(const float* W_ih, const float* W_hh, int k, int j) {
    // x = [ctx(64), h(64)]
    return (k < HID) ? W_ih[j * (EMB + HID) + EMB + k] : W_hh[j * HID + (k - HID)];
}

__global__ void setup_WTh(const float* __restrict__ W_ih,
                          const float* __restrict__ W_hh) {
    int k2 = blockIdx.x, j = threadIdx.x;   // k2 in [0,64)
    float w0 = wt_elem(W_ih, W_hh, 2 * k2 + 0, j);
    float w1 = wt_elem(W_ih, W_hh, 2 * k2 + 1, j);
    g_WTh[k2 * GATES + j] = __floats2half2_rn(w0, w1);
}

__global__ void setup_fcT(const float* __restrict__ fc_W) {
    int d = blockIdx.x, v = threadIdx.x;   // grid 128, block 32
    g_fcT[d * 32 + v] = (v < VOCAB) ? fc_W[v * 2 * HID + d] : 0.0f;
}

__device__ __forceinline__ float fsigmoid(float x) {
    return __fdividef(1.0f, 1.0f + __expf(-fmaxf(x, -80.0f)));
}
__device__ __forceinline__ float ftanh(float x) {
    float e = __expf(fminf(2.0f * x, 80.0f));
    return 1.0f - __fdividef(2.0f, e + 1.0f);
}

__global__ __launch_bounds__(256, 2)
void decoder_kernel(const int* __restrict__ y,
                    const float* __restrict__ h0,
                    const float* __restrict__ c0,
                    const float* __restrict__ enc,
                    const float* __restrict__ fc_b,
                    float* __restrict__ out) {
    extern __shared__ char smem_raw[];
    Smem& S = *reinterpret_cast<Smem*>(smem_raw);

    const int tid  = threadIdx.x;
    const int lane = tid & 31;
    const int wid  = tid >> 5;
    const int b    = blockIdx.x;

    // Gate ownership: 4 adjacent lanes hold the 4 gates (i,f,g,o) of hidden dim j.
    const int q    = tid & 3;          // 0:i 1:f 2:g 3:o
    const int j    = tid >> 2;         // hidden dim [0,64)
    const int gidx = q * 64 + j;       // row in canonical 256-gate order

    // ---- Gate weights in registers: full 128-weight column as 64 half2 ----
    __half2 W2[64];
#pragma unroll
    for (int i = 0; i < 64; i++)
        W2[i] = g_WTh[i * GATES + gidx];

    // ---- Prologue: enc -> fp32 shared (padded rows), coalesced float4 ----
    {
        const float4* esrc = reinterpret_cast<const float4*>(enc) + (size_t)b * (SLEN * HID / 4);
#pragma unroll
        for (int it = 0; it < 16; it++) {
            int idx = tid + it * 256;              // 4096 float4s
            int s = idx >> 4, qq = idx & 15;
            *reinterpret_cast<float4*>(&S.enc[s * ENCPAD + qq * 4]) = esrc[idx];
        }
    }
    float c_reg = (q == 0) ? c0[b * HID + j] : 0.0f;
    if (tid < HID) S.h[0][tid] = h0[b * HID + tid];
    if (tid < TSTEPS) S.ybuf[tid] = y[b * TSTEPS + tid];
    __syncthreads();

    const ulonglong2* erow2 = reinterpret_cast<const ulonglong2*>(&S.enc[tid * ENCPAD]);
    const ulonglong2* ctx2  = reinterpret_cast<const ulonglong2*>(S.ctx);

    // ---- Timestep loop ----
    for (int t = 0; t < TSTEPS; t++) {
        const int oldb = t & 1, newb = oldb ^ 1;
        const ulonglong2* hOld2 = reinterpret_cast<const ulonglong2*>(S.h[oldb]);

        // Phase A: score[s=tid] = enc[s,:].h ; p = exp(score); store (p,p) packed + warp sums.
        {
            u64 a0 = 0ull, a1 = 0ull;
#pragma unroll
            for (int k = 0; k < 16; k++) {
                ulonglong2 e  = erow2[k];
                ulonglong2 hh = hOld2[k];
                fma2(a0, e.x, hh.x);
                fma2(a1, e.y, hh.y);
            }
            float2 f0 = up2(a0), f1 = up2(a1);
            float p = __expf((f0.x + f0.y) + (f1.x + f1.y));
            S.pp[tid] = pk2(p, p);
            float ws = p;
#pragma unroll
            for (int o = 16; o; o >>= 1) ws += __shfl_xor_sync(~0u, ws, o);
            if (lane == 0) S.wsum[wid] = ws;
        }
        __syncwarp();   // pp[s] is produced and consumed within the same warp

        // Phase B: context partials. Warp w covers s in [32w,32w+32).
        // lanes 0-15 -> even s, 16-31 -> odd s; lane handles 4 h values.
        {
            const int hi = lane >> 4, lo = lane & 15;
            const char* ebase = reinterpret_cast<const char*>(
                &S.enc[(wid * 32 + hi) * ENCPAD + lo * 4]);
            const u64* ppb = &S.pp[wid * 32 + hi];
            u64 a0 = 0ull, a1 = 0ull;
#pragma unroll
            for (int i = 0; i < 16; i++) {
                u64 ppv = ppb[2 * i];                               // broadcast LDS.64
                ulonglong2 e = *reinterpret_cast<const ulonglong2*>(
                    ebase + (size_t)i * (2 * ENCPAD * 4));
                fma2(a0, e.x, ppv);
                fma2(a1, e.y, ppv);
            }
            float2 r0 = up2(a0), r1 = up2(a1);
            *reinterpret_cast<float4*>(&S.cp[wid][hi][lo * 4]) =
                make_float4(r0.x, r0.y, r1.x, r1.y);
        }
        __syncthreads();   // (1)

        // Phase C: reduce partials + normalize -> ctx
        if (tid < HID) {
            float z = S.wsum[0];
#pragma unroll
            for (int i = 1; i < 8; i++) z += S.wsum[i];
            float a = 0.f;
#pragma unroll
            for (int w = 0; w < 8; w++) a += S.cp[w][0][tid] + S.cp[w][1][tid];
            S.ctx[tid] = a * __fdividef(1.0f, z);
        }
        __syncthreads();   // (2)

        // Phase D+E fused: gate gidx = 128-dot (fp16 reg weights, f32x2 FMAs),
        // in-warp shuffle gathers i/f/g/o of dim j, q==0 lanes update c/h.
        {
            u64 a0 = 0ull, a1 = 0ull, a2 = 0ull, a3 = 0ull;
#pragma unroll
            for (int i = 0; i < 16; i++) {
                ulonglong2 x = ctx2[i];
                float2 wa = __half22float2(W2[2 * i]);
                float2 wb = __half22float2(W2[2 * i + 1]);
                fma2(a0, x.x, pk2(wa.x, wa.y));
                fma2(a1, x.y, pk2(wb.x, wb.y));
            }
#pragma unroll
            for (int i = 0; i < 16; i++) {
                ulonglong2 x = hOld2[i];
                float2 wa = __half22float2(W2[32 + 2 * i]);
                float2 wb = __half22float2(W2[33 + 2 * i]);
                fma2(a2, x.x, pk2(wa.x, wa.y));
                fma2(a3, x.y, pk2(wb.x, wb.y));
            }
            float2 s0 = up2(a0), s1 = up2(a1), s2 = up2(a2), s3 = up2(a3);
            int v = S.ybuf[t];
            float gate = ((s0.x + s0.y) + (s1.x + s1.y))
                       + ((s2.x + s2.y) + (s3.x + s3.y))
                       + __ldg(&g_vocabW[v * GATES + gidx]);
            float a = (q == 2) ? ftanh(gate) : fsigmoid(gate);

            int lb = lane & ~3;
            float ai = __shfl_sync(~0u, a, lb + 0);
            float af = __shfl_sync(~0u, a, lb + 1);
            float ag = __shfl_sync(~0u, a, lb + 2);
            float ao = __shfl_sync(~0u, a, lb + 3);
            if (q == 0) {
                c_reg = af * c_reg + ai * ag;
                S.h[newb][j] = ao * ftanh(c_reg);
            }
        }
        __syncthreads();   // (3)

        // Phase F: logits partials. Warp w covers d in [16w,16w+16); lane = vocab slot.
        {
            const float4* sF4 = (wid < 4) ? reinterpret_cast<const float4*>(S.h[newb])
                                          : reinterpret_cast<const float4*>(S.ctx);
            int qq = (wid & 3) * 4;
            float4 s0 = sF4[qq], s1 = sF4[qq + 1], s2 = sF4[qq + 2], s3 = sF4[qq + 3];
            const float* fc = &g_fcT[(wid * 16) * 32 + lane];
            float acc;
            acc  = s0.x * __ldg(fc +  0 * 32);
            acc += s0.y * __ldg(fc +  1 * 32);
            acc += s0.z * __ldg(fc +  2 * 32);
            acc += s0.w * __ldg(fc +  3 * 32);
            acc += s1.x * __ldg(fc +  4 * 32);
            acc += s1.y * __ldg(fc +  5 * 32);
            acc += s1.z * __ldg(fc +  6 * 32);
            acc += s1.w * __ldg(fc +  7 * 32);
            acc += s2.x * __ldg(fc +  8 * 32);
            acc += s2.y * __ldg(fc +  9 * 32);
            acc += s2.z * __ldg(fc + 10 * 32);
            acc += s2.w * __ldg(fc + 11 * 32);
            acc += s3.x * __ldg(fc + 12 * 32);
            acc += s3.y * __ldg(fc + 13 * 32);
            acc += s3.z * __ldg(fc + 14 * 32);
            acc += s3.w * __ldg(fc + 15 * 32);
            S.fp[wid][lane] = acc;
        }
        __syncthreads();   // (4)

        if (tid < VOCAB) {
            float acc = __ldg(&fc_b[tid]);
#pragma unroll
            for (int w = 0; w < 8; w++) acc += S.fp[w][tid];
            out[((size_t)b * TSTEPS + t) * VOCAB + tid] = acc;
        }
        // No trailing barrier: S.fp is next written after 3 barriers of t+1;
        // all other cross-phase hazards audited against barriers (1)-(4).
    }
}

extern "C" void kernel_launch(void* const* d_in, const int* in_sizes, int n_in,
                              void* d_out, int out_size) {
    const int*   y     = (const int*)  d_in[0];
    const float* h0    = (const float*)d_in[1];
    const float* c0    = (const float*)d_in[2];
    const float* enc   = (const float*)d_in[3];
    const float* emb   = (const float*)d_in[4];
    const float* W_ih  = (const float*)d_in[5];
    const float* W_hh  = (const float*)d_in[6];
    const float* b_ih  = (const float*)d_in[7];
    const float* b_hh  = (const float*)d_in[8];
    const float* fc_W  = (const float*)d_in[9];
    const float* fc_b  = (const float*)d_in[10];
    float* out = (float*)d_out;
    (void)in_sizes; (void)n_in; (void)out_size;

    setup_vocabW<<<VOCAB, GATES>>>(emb, W_ih, b_ih, b_hh);
    setup_WTh<<<64, GATES>>>(W_ih, W_hh);
    setup_fcT<<<128, 32>>>(fc_W);

    cudaFuncSetAttribute(decoder_kernel,
                         cudaFuncAttributeMaxDynamicSharedMemorySize,
                         (int)sizeof(Smem));
    decoder_kernel<<<BATCH, 256, sizeof(Smem)>>>(y, h0, c0, enc, fc_b, out);
}

// round 12
// speedup vs baseline: 1.7363x; 1.1480x over previous
#include <cuda_runtime.h>
#include <cuda_fp16.h>

#define BATCH   2048
#define TSTEPS  128
#define SLEN    256
#define HID     64
#define EMB     32
#define VOCAB   29
#define GATES   256          // 4*HID
#define ROWH2   36           // enc row stride in half2 units (144 B; bank-conflict-free)

typedef unsigned long long u64;

// f32x2 packed-FMA helpers (sm_100+ PTX; ptxas never emits FFMA2 from C++)
__device__ __forceinline__ u64 pk2(float x, float y) {
    u64 r; asm("mov.b64 %0, {%1, %2};" : "=l"(r) : "f"(x), "f"(y)); return r;
}
__device__ __forceinline__ float2 up2(u64 v) {
    float2 r; asm("mov.b64 {%0, %1}, %2;" : "=f"(r.x), "=f"(r.y) : "l"(v)); return r;
}
__device__ __forceinline__ void fma2(u64& d, u64 a, u64 b) {
    asm("fma.rn.f32x2 %0, %1, %2, %0;" : "+l"(d) : "l"(a), "l"(b));
}

// Precomputed tables (device globals — allocation-free scratch)
__device__ float   g_vocabW[VOCAB * GATES];   // emb@W_ih[:, :32]^T + b_ih + b_hh  (fp32)
__device__ __half2 g_WTh[64 * GATES];         // g_WTh[k2*256+j] = (WT[2k2][j], WT[2k2+1][j]) fp16
__device__ float   g_fcT[128 * 32];           // fcT[d][v] = fc_W[v][d] (v<29 else 0); d: [h(64), ctx(64)]

struct __align__(16) Smem {
    __half2 ench[SLEN * ROWH2];  // 36864 B  enc fp16 pairs, padded rows
    u64     pp[SLEN];            //  2048 B  (p,p) packed pairs
    float   cp[8][2][HID];       //  4096 B  context partials [warp][s-parity][h]
    float   h[2][HID];           //   512 B  double-buffered hidden state
    float   ctx[HID];            //   256 B
    float   fp[8][32];           //  1024 B  fc partials
    float   wsum[8];             //    32 B
    int     ybuf[TSTEPS];        //   512 B
};  // ~45.3 KB -> 2 CTAs/SM

__global__ void setup_vocabW(const float* __restrict__ emb,
                             const float* __restrict__ W_ih,
                             const float* __restrict__ b_ih,
                             const float* __restrict__ b_hh) {
    int v = blockIdx.x, j = threadIdx.x;
    float acc = b_ih[j] + b_hh[j];
#pragma unroll
    for (int e = 0; e < EMB; e++)
        acc += emb[v * EMB + e] * W_ih[j * (EMB + HID) + e];
    g_vocabW[v * GATES + j] = acc;
}

__device__ __forceinline__ float wt_elem(const float* W_ih, const float* W_hh, int k, int j) {
    // x = [ctx(64), h(64)]
    return (k < HID) ? W_ih[j * (EMB + HID) + EMB + k] : W_hh[j * HID + (k - HID)];
}

__global__ void setup_WTh(const float* __restrict__ W_ih,
                          const float* __restrict__ W_hh) {
    int k2 = blockIdx.x, j = threadIdx.x;   // k2 in [0,64)
    float w0 = wt_elem(W_ih, W_hh, 2 * k2 + 0, j);
    float w1 = wt_elem(W_ih, W_hh, 2 * k2 + 1, j);
    g_WTh[k2 * GATES + j] = __floats2half2_rn(w0, w1);
}

__global__ void setup_fcT(const float* __restrict__ fc_W) {
    int d = blockIdx.x, v = threadIdx.x;   // grid 128, block 32
    g_fcT[d * 32 + v] = (v < VOCAB) ? fc_W[v * 2 * HID + d] : 0.0f;
}

__device__ __forceinline__ float fsigmoid(float x) {
    return __fdividef(1.0f, 1.0f + __expf(-fmaxf(x, -80.0f)));
}
__device__ __forceinline__ float ftanh(float x) {
    float e = __expf(fminf(2.0f * x, 80.0f));
    return 1.0f - __fdividef(2.0f, e + 1.0f);
}

__global__ __launch_bounds__(256, 2)
void decoder_kernel(const int* __restrict__ y,
                    const float* __restrict__ h0,
                    const float* __restrict__ c0,
                    const float* __restrict__ enc,
                    const float* __restrict__ fc_b,
                    float* __restrict__ out) {
    extern __shared__ char smem_raw[];
    Smem& S = *reinterpret_cast<Smem*>(smem_raw);

    const int tid  = threadIdx.x;
    const int lane = tid & 31;
    const int wid  = tid >> 5;
    const int b    = blockIdx.x;

    // Gate ownership: 4 adjacent lanes hold the 4 gates (i,f,g,o) of hidden dim j.
    const int q    = tid & 3;          // 0:i 1:f 2:g 3:o
    const int j    = tid >> 2;         // hidden dim [0,64)
    const int gidx = q * 64 + j;       // row in canonical 256-gate order

    // ---- Gate weights in registers: full 128-weight column as 64 half2 ----
    __half2 W2[64];
#pragma unroll
    for (int i = 0; i < 64; i++)
        W2[i] = g_WTh[i * GATES + gidx];

    // ---- Prologue: enc -> fp16 shared (padded rows), coalesced float4 loads ----
    {
        const float4* esrc = reinterpret_cast<const float4*>(enc) + (size_t)b * (SLEN * HID / 4);
#pragma unroll
        for (int it = 0; it < 16; it++) {
            int idx = tid + it * 256;              // 4096 float4s
            int s = idx >> 4, qq = idx & 15;       // qq: 4-float chunk within row
            float4 v = esrc[idx];
            __half2* dst = &S.ench[s * ROWH2 + 2 * qq];
            dst[0] = __floats2half2_rn(v.x, v.y);
            dst[1] = __floats2half2_rn(v.z, v.w);
        }
    }
    float c_reg = (q == 0) ? c0[b * HID + j] : 0.0f;
    if (tid < HID) S.h[0][tid] = h0[b * HID + tid];
    if (tid < TSTEPS) S.ybuf[tid] = y[b * TSTEPS + tid];
    __syncthreads();

    const uint4*      erow4 = reinterpret_cast<const uint4*>(&S.ench[tid * ROWH2]);
    const ulonglong2* ctx2  = reinterpret_cast<const ulonglong2*>(S.ctx);

    // ---- Timestep loop ----
    for (int t = 0; t < TSTEPS; t++) {
        const int oldb = t & 1, newb = oldb ^ 1;
        const ulonglong2* hOld2 = reinterpret_cast<const ulonglong2*>(S.h[oldb]);

        // Phase A: score[s=tid] = enc16[s,:].h ; p = exp(score); (p,p) packed + warp sums.
        {
            u64 a0 = 0ull, a1 = 0ull;
#pragma unroll
            for (int k = 0; k < 8; k++) {
                uint4 ev = erow4[k];                       // 8 halves of own row
                ulonglong2 hh0 = hOld2[2 * k];             // 4 fp32 h (broadcast)
                ulonglong2 hh1 = hOld2[2 * k + 1];
                float2 e0 = __half22float2(*reinterpret_cast<__half2*>(&ev.x));
                float2 e1 = __half22float2(*reinterpret_cast<__half2*>(&ev.y));
                float2 e2 = __half22float2(*reinterpret_cast<__half2*>(&ev.z));
                float2 e3 = __half22float2(*reinterpret_cast<__half2*>(&ev.w));
                fma2(a0, pk2(e0.x, e0.y), hh0.x);
                fma2(a0, pk2(e1.x, e1.y), hh0.y);
                fma2(a1, pk2(e2.x, e2.y), hh1.x);
                fma2(a1, pk2(e3.x, e3.y), hh1.y);
            }
            float2 f0 = up2(a0), f1 = up2(a1);
            float p = __expf((f0.x + f0.y) + (f1.x + f1.y));
            S.pp[tid] = pk2(p, p);
            float ws = p;
#pragma unroll
            for (int o = 16; o; o >>= 1) ws += __shfl_xor_sync(~0u, ws, o);
            if (lane == 0) S.wsum[wid] = ws;
        }
        __syncwarp();   // pp[s] produced and consumed within the same warp

        // Phase B: context partials. Warp w covers s in [32w,32w+32).
        // lanes 0-15 -> even s, 16-31 -> odd s; lane handles 4 h values (LDS.64).
        {
            const int hi = lane >> 4, lo = lane & 15;
            const __half2* ebase = &S.ench[(wid * 32 + hi) * ROWH2 + lo * 2];
            const u64* ppb = &S.pp[wid * 32 + hi];
            u64 a0 = 0ull, a1 = 0ull;
#pragma unroll
            for (int i = 0; i < 16; i++) {
                u64 ppv = ppb[2 * i];                      // broadcast LDS.64
                uint2 e = *reinterpret_cast<const uint2*>(ebase + (size_t)i * 2 * ROWH2);
                float2 f0 = __half22float2(*reinterpret_cast<__half2*>(&e.x));
                float2 f1 = __half22float2(*reinterpret_cast<__half2*>(&e.y));
                fma2(a0, pk2(f0.x, f0.y), ppv);
                fma2(a1, pk2(f1.x, f1.y), ppv);
            }
            float2 r0 = up2(a0), r1 = up2(a1);
            *reinterpret_cast<float4*>(&S.cp[wid][hi][lo * 4]) =
                make_float4(r0.x, r0.y, r1.x, r1.y);
        }
        __syncthreads();   // (1)

        // Phase D-h (pre-barrier): h-half of the gate dot — depends only on hOld,
        // runs concurrently with Phase C's ctx reduction on warps 0-1.
        float hsum;
        {
            u64 a2 = 0ull, a3 = 0ull;
#pragma unroll
            for (int i = 0; i < 16; i++) {
                ulonglong2 x = hOld2[i];
                float2 wa = __half22float2(W2[32 + 2 * i]);
                float2 wb = __half22float2(W2[33 + 2 * i]);
                fma2(a2, x.x, pk2(wa.x, wa.y));
                fma2(a3, x.y, pk2(wb.x, wb.y));
            }
            float2 s2 = up2(a2), s3 = up2(a3);
            hsum = (s2.x + s2.y) + (s3.x + s3.y);
        }

        // Phase C: reduce partials + normalize -> ctx (threads 0-63)
        if (tid < HID) {
            float z = S.wsum[0];
#pragma unroll
            for (int i = 1; i < 8; i++) z += S.wsum[i];
            float a = 0.f;
#pragma unroll
            for (int w = 0; w < 8; w++) a += S.cp[w][0][tid] + S.cp[w][1][tid];
            S.ctx[tid] = a * __fdividef(1.0f, z);
        }
        __syncthreads();   // (2)

        // Phase D-ctx + E: ctx-half of gate dot, combine, activate; in-warp shuffle
        // gathers i/f/g/o of dim j; q==0 lanes update c (register) and h[newb].
        {
            u64 a0 = 0ull, a1 = 0ull;
#pragma unroll
            for (int i = 0; i < 16; i++) {
                ulonglong2 x = ctx2[i];
                float2 wa = __half22float2(W2[2 * i]);
                float2 wb = __half22float2(W2[2 * i + 1]);
                fma2(a0, x.x, pk2(wa.x, wa.y));
                fma2(a1, x.y, pk2(wb.x, wb.y));
            }
            float2 s0 = up2(a0), s1 = up2(a1);
            int v = S.ybuf[t];
            float gate = ((s0.x + s0.y) + (s1.x + s1.y)) + hsum
                       + __ldg(&g_vocabW[v * GATES + gidx]);
            float a = (q == 2) ? ftanh(gate) : fsigmoid(gate);

            int lb = lane & ~3;
            float ai = __shfl_sync(~0u, a, lb + 0);
            float af = __shfl_sync(~0u, a, lb + 1);
            float ag = __shfl_sync(~0u, a, lb + 2);
            float ao = __shfl_sync(~0u, a, lb + 3);
            if (q == 0) {
                c_reg = af * c_reg + ai * ag;
                S.h[newb][j] = ao * ftanh(c_reg);
            }
        }
        __syncthreads();   // (3)

        // Phase F: logits partials. Warp w covers d in [16w,16w+16); lane = vocab slot.
        {
            const float4* sF4 = (wid < 4) ? reinterpret_cast<const float4*>(S.h[newb])
                                          : reinterpret_cast<const float4*>(S.ctx);
            int qq = (wid & 3) * 4;
            float4 s0 = sF4[qq], s1 = sF4[qq + 1], s2 = sF4[qq + 2], s3 = sF4[qq + 3];
            const float* fc = &g_fcT[(wid * 16) * 32 + lane];
            float acc;
            acc  = s0.x * __ldg(fc +  0 * 32);
            acc += s0.y * __ldg(fc +  1 * 32);
            acc += s0.z * __ldg(fc +  2 * 32);
            acc += s0.w * __ldg(fc +  3 * 32);
            acc += s1.x * __ldg(fc +  4 * 32);
            acc += s1.y * __ldg(fc +  5 * 32);
            acc += s1.z * __ldg(fc +  6 * 32);
            acc += s1.w * __ldg(fc +  7 * 32);
            acc += s2.x * __ldg(fc +  8 * 32);
            acc += s2.y * __ldg(fc +  9 * 32);
            acc += s2.z * __ldg(fc + 10 * 32);
            acc += s2.w * __ldg(fc + 11 * 32);
            acc += s3.x * __ldg(fc + 12 * 32);
            acc += s3.y * __ldg(fc + 13 * 32);
            acc += s3.z * __ldg(fc + 14 * 32);
            acc += s3.w * __ldg(fc + 15 * 32);
            S.fp[wid][lane] = acc;
        }
        __syncthreads();   // (4)

        if (tid < VOCAB) {
            float acc = __ldg(&fc_b[tid]);
#pragma unroll
            for (int w = 0; w < 8; w++) acc += S.fp[w][tid];
            out[((size_t)b * TSTEPS + t) * VOCAB + tid] = acc;
        }
        // No trailing barrier: S.fp is next written after 3 barriers of t+1;
        // all other cross-phase hazards audited against barriers (1)-(4).
    }
}

extern "C" void kernel_launch(void* const* d_in, const int* in_sizes, int n_in,
                              void* d_out, int out_size) {
    const int*   y     = (const int*)  d_in[0];
    const float* h0    = (const float*)d_in[1];
    const float* c0    = (const float*)d_in[2];
    const float* enc   = (const float*)d_in[3];
    const float* emb   = (const float*)d_in[4];
    const float* W_ih  = (const float*)d_in[5];
    const float* W_hh  = (const float*)d_in[6];
    const float* b_ih  = (const float*)d_in[7];
    const float* b_hh  = (const float*)d_in[8];
    const float* fc_W  = (const float*)d_in[9];
    const float* fc_b  = (const float*)d_in[10];
    float* out = (float*)d_out;
    (void)in_sizes; (void)n_in; (void)out_size;

    setup_vocabW<<<VOCAB, GATES>>>(emb, W_ih, b_ih, b_hh);
    setup_WTh<<<64, GATES>>>(W_ih, W_hh);
    setup_fcT<<<128, 32>>>(fc_W);

    cudaFuncSetAttribute(decoder_kernel,
                         cudaFuncAttributeMaxDynamicSharedMemorySize,
                         (int)sizeof(Smem));
    decoder_kernel<<<BATCH, 256, sizeof(Smem)>>>(y, h0, c0, enc, fc_b, out);
}